// round 13
// baseline (speedup 1.0000x reference)
#include <cuda_runtime.h>
#include <cuda_bf16.h>
#include <cstdint>

#define B 512
#define NN 64
#define NE 1024
#define DD 128
#define BN (B*NN)
#define BE (B*NE)
#define LDP 68

__device__ __align__(16) uint32_t g_Wpk[9][2][DD*64];
__device__ __align__(16) uint32_t g_W5pk[2][DD*64];
__device__ __align__(16) float g_P0[DD*DD];
__device__ __align__(16) float g_c5[DD];
__device__ __align__(16) float g_s0[BN*DD];
__device__ float g_rs[BN];
__device__ float g_respart[(BE/64)*DD];
__device__ float g_resid[B*DD];
__device__ float g_attl[BN];

__device__ __forceinline__ float sigf(float x){ return 1.f/(1.f+__expf(-x)); }
__device__ __forceinline__ void split2(float x0, float x1, uint32_t& hi, uint32_t& lo){
    __nv_bfloat162 h = __floats2bfloat162_rn(x0, x1);
    __nv_bfloat162 l = __floats2bfloat162_rn(x0-__low2float(h), x1-__high2float(h));
    hi = *reinterpret_cast<uint32_t*>(&h);
    lo = *reinterpret_cast<uint32_t*>(&l);
}
__device__ __forceinline__ float unpk(uint32_t h, uint32_t l, int half){
    __nv_bfloat162 hb = *reinterpret_cast<__nv_bfloat162*>(&h);
    __nv_bfloat162 lb = *reinterpret_cast<__nv_bfloat162*>(&l);
    return half ? (__high2float(hb)+__high2float(lb)) : (__low2float(hb)+__low2float(lb));
}
__device__ __forceinline__ void mma16(float c[4], const uint32_t a[4], const uint32_t b[2]){
    asm volatile("mma.sync.aligned.m16n8k16.row.col.f32.bf16.bf16.f32 "
        "{%0,%1,%2,%3}, {%4,%5,%6,%7}, {%8,%9}, {%0,%1,%2,%3};"
        : "+f"(c[0]),"+f"(c[1]),"+f"(c[2]),"+f"(c[3])
        : "r"(a[0]),"r"(a[1]),"r"(a[2]),"r"(a[3]),"r"(b[0]),"r"(b[1]));
}

// 3-term split GEMM, A in smem [m][kp] ld LDA, B in smem [n][kp] ld LDB
template<int MI,int LDA,int LDB,int KS>
__device__ __forceinline__ void gemm3(const uint32_t* Ah, const uint32_t* Al,
                                      const uint32_t* Bh, const uint32_t* Bl,
                                      int wm, int wn, int lane, float (*acc)[4]){
    #pragma unroll
    for(int ks=0;ks<KS;ks++){
        const int kp = ks*8 + (lane&3);
        uint32_t ah[MI][4], al[MI][4];
        #pragma unroll
        for(int mi=0;mi<MI;mi++){
            int ro = (wm+16*mi+(lane>>2))*LDA + kp;
            ah[mi][0]=Ah[ro]; ah[mi][1]=Ah[ro+8*LDA]; ah[mi][2]=Ah[ro+4]; ah[mi][3]=Ah[ro+8*LDA+4];
            al[mi][0]=Al[ro]; al[mi][1]=Al[ro+8*LDA]; al[mi][2]=Al[ro+4]; al[mi][3]=Al[ro+8*LDA+4];
        }
        #pragma unroll
        for(int ni=0;ni<4;ni++){
            int ro = (wn+8*ni+(lane>>2))*LDB + kp;
            uint32_t bh[2]={Bh[ro],Bh[ro+4]}, bl_[2]={Bl[ro],Bl[ro+4]};
            #pragma unroll
            for(int mi=0;mi<MI;mi++){
                mma16(acc[mi*4+ni], ah[mi], bh);
                mma16(acc[mi*4+ni], al[mi], bh);
                mma16(acc[mi*4+ni], ah[mi], bl_);
            }
        }
    }
}

// 3-term split GEMM, A in smem (ld LDP), B read DIRECTLY from global packed slab [n=128][kp=64]
template<int MI,int KS>
__device__ __forceinline__ void gemm3g(const uint32_t* Ah, const uint32_t* Al,
                                       const uint32_t* __restrict__ Gh,
                                       const uint32_t* __restrict__ Gl,
                                       int wm, int wn, int lane, float (*acc)[4]){
    #pragma unroll
    for(int ks=0;ks<KS;ks++){
        const int kp = ks*8 + (lane&3);
        uint32_t ah[MI][4], al[MI][4];
        #pragma unroll
        for(int mi=0;mi<MI;mi++){
            int ro = (wm+16*mi+(lane>>2))*LDP + kp;
            ah[mi][0]=Ah[ro]; ah[mi][1]=Ah[ro+8*LDP]; ah[mi][2]=Ah[ro+4]; ah[mi][3]=Ah[ro+8*LDP+4];
            al[mi][0]=Al[ro]; al[mi][1]=Al[ro+8*LDP]; al[mi][2]=Al[ro+4]; al[mi][3]=Al[ro+8*LDP+4];
        }
        #pragma unroll
        for(int ni=0;ni<4;ni++){
            int ro = (wn+8*ni+(lane>>2))*64 + kp;
            uint32_t bh[2]={__ldg(Gh+ro),__ldg(Gh+ro+4)};
            uint32_t bl_[2]={__ldg(Gl+ro),__ldg(Gl+ro+4)};
            #pragma unroll
            for(int mi=0;mi<MI;mi++){
                mma16(acc[mi*4+ni], ah[mi], bh);
                mma16(acc[mi*4+ni], al[mi], bh);
                mma16(acc[mi*4+ni], ah[mi], bl_);
            }
        }
    }
}

#define FOREACH(MI_, ...) \
  {_Pragma("unroll") for(int mi=0;mi<MI_;mi++) \
  _Pragma("unroll") for(int h=0;h<2;h++){ \
    int rl=wm+16*mi+8*h+(lane>>2); (void)rl; \
    _Pragma("unroll") for(int ni=0;ni<4;ni++){ \
      int f=mi*4+ni; int col=wn+8*ni+(lane&3)*2; (void)f; (void)col; __VA_ARGS__ } }}
#define ZERO(A,NF) {_Pragma("unroll") for(int f_=0;f_<NF;f_++){A[f_][0]=A[f_][1]=A[f_][2]=A[f_][3]=0.f;}}

template<int R>
__device__ __forceinline__ void split_tile(uint32_t* dh, uint32_t* dl,
                                           const float* __restrict__ src, int tid){
    #pragma unroll
    for(int i=0;i<R/8;i++){
        int idx=i*256+tid; int r=idx>>5, c=idx&31;
        float4 v=*(const float4*)(src+(long)r*DD+c*4);
        uint32_t h0,l0,h1,l1; split2(v.x,v.y,h0,l0); split2(v.z,v.w,h1,l1);
        dh[r*LDP+c*2]=h0; dh[r*LDP+c*2+1]=h1;
        dl[r*LDP+c*2]=l0; dl[r*LDP+c*2+1]=l1;
    }
}

// ---------------- setup ----------------
// slab packs (9 blocks) + c5 Horner (block 9)
__global__ void __launch_bounds__(256) k_prep(
    const float* __restrict__ Wl, const float* __restrict__ Wr,
    const float* __restrict__ Wz, const float* __restrict__ Wh,
    const float* __restrict__ Wo, const float* __restrict__ Wa1,
    const float* __restrict__ bl){
    __shared__ float c[DD];
    int bi=blockIdx.x, tid=threadIdx.x;
    if(bi==9){
        if(tid<DD) c[tid]=0.f;
        __syncthreads();
        for(int t=0;t<5;t++){
            float a=0.f;
            if(tid<DD){
                a=bl[tid];
                const float4* W4=(const float4*)(Wl+tid*DD);
                #pragma unroll 8
                for(int k=0;k<32;k++){ float4 w=W4[k];
                    a += w.x*c[4*k]+w.y*c[4*k+1]+w.z*c[4*k+2]+w.w*c[4*k+3]; }
            }
            __syncthreads(); if(tid<DD) c[tid]=a; __syncthreads();
        }
        if(tid<DD) g_c5[tid]=c[tid];
        return;
    }
    const float* S[9]={Wl,Wz,Wz,Wr,Wr,Wh,Wh,Wo,Wa1};
    const int ST[9]={128,256,256,256,256,256,256,128,128};
    const int OF[9]={0,0,128,0,128,0,128,0,0};
    const float* src=S[bi]; int strd=ST[bi], off=OF[bi];
    for(int idx=tid; idx<DD*64; idx+=256){
        int r=idx>>6, kp=idx&63;
        const float* p=src+(long)r*strd+off+2*kp;
        uint32_t h,l; split2(p[0],p[1],h,l);
        g_Wpk[bi][0][idx]=h; g_Wpk[bi][1][idx]=l;
    }
}
// W2 = W@W
__global__ void __launch_bounds__(1024) k_sqmmA(const float* __restrict__ Wl){
    extern __shared__ float s[];
    float* sY=s; float* sX=s+DD*DD;
    int tid=threadIdx.x;
    #pragma unroll
    for(int j=0;j<16;j++) sY[j*1024+tid]=Wl[j*1024+tid];
    int r0=blockIdx.x*8;
    sX[tid]=Wl[r0*DD+tid];
    __syncthreads();
    int ty=tid>>7, o=tid&127;
    float acc=0.f;
    #pragma unroll 16
    for(int m=0;m<DD;m++) acc += sX[ty*DD+m]*sY[m*DD+o];
    g_P0[(r0+ty)*DD+o]=acc;
}
// W5 rows = (W2row @ W2) @ W, packed directly
__global__ void __launch_bounds__(1024) k_sqmmB(const float* __restrict__ Wl){
    extern __shared__ float s[];
    float* sW2=s; float* sW=s+DD*DD; float* sA=s+2*DD*DD;
    int tid=threadIdx.x;
    #pragma unroll
    for(int j=0;j<16;j++){ sW2[j*1024+tid]=g_P0[j*1024+tid]; sW[j*1024+tid]=Wl[j*1024+tid]; }
    __syncthreads();
    int r=tid>>7, o=tid&127, R=blockIdx.x*8+r;
    float a=0.f;
    #pragma unroll 16
    for(int k=0;k<DD;k++) a += sW2[R*DD+k]*sW2[k*DD+o];
    sA[tid]=a;
    __syncthreads();
    float b=0.f;
    #pragma unroll 16
    for(int k=0;k<DD;k++) b += sA[r*DD+k]*sW[k*DD+o];
    __syncthreads();
    sA[tid]=b;
    __syncthreads();
    if(tid<512){
        int rr=tid>>6, kp=tid&63;
        uint32_t h,l; split2(sA[rr*DD+2*kp], sA[rr*DD+2*kp+1], h, l);
        g_W5pk[0][(blockIdx.x*8+rr)*64+kp]=h;
        g_W5pk[1][(blockIdx.x*8+rr)*64+kp]=l;
    }
}

// ---------------- s0 = A @ e0 per batch + rowsum(A) ----------------
__global__ void __launch_bounds__(256) k_s0(const float* __restrict__ A,
                                            const float* __restrict__ E0){
    extern __shared__ uint32_t sm[];
    float*    sF  =(float*)sm;      // [64][132]
    uint32_t* sAh = sm+8448;        // [64][36]
    uint32_t* sAl = sm+10752;
    uint32_t* sEh = sm+13056;       // [128][36]
    uint32_t* sEl = sm+17664;
    const int tid=threadIdx.x, lane=tid&31, wid=tid>>5;
    const int wm=(wid>>2)*32, wn=(wid&3)*32;
    const int g=lane>>2, q=lane&3;
    const int bb=blockIdx.x;
    const float* Ab=A +(long)bb*NN*NE;
    const float* Eb=E0+(long)bb*NE*DD;
    float acc[8][4]={}; float rsum=0.f;
    for(int kc=0;kc<16;kc++){
        const int kb=kc*64;
        #pragma unroll
        for(int i=0;i<4;i++){
            int idx=i*256+tid; int r=idx>>4, cq=idx&15;
            float4 v=*(const float4*)(Ab+(long)r*NE+kb+cq*4);
            uint32_t h0,l0,h1,l1; split2(v.x,v.y,h0,l0); split2(v.z,v.w,h1,l1);
            sAh[r*36+cq*2]=h0; sAh[r*36+cq*2+1]=h1;
            sAl[r*36+cq*2]=l0; sAl[r*36+cq*2+1]=l1;
        }
        #pragma unroll
        for(int i=0;i<8;i++){
            int idx=i*256+tid; int r=idx>>5, c=idx&31;
            *(float4*)(sF+r*132+c*4)=*(const float4*)(Eb+(long)(kb+r)*DD+c*4);
        }
        __syncthreads();
        #pragma unroll
        for(int ii=0;ii<16;ii++){
            int n =(ii&3)*32+(wid&3)*8+g;
            int kp=(ii>>2)*8+(wid>>2)*4+q;
            uint32_t h,l; split2(sF[(2*kp)*132+n], sF[(2*kp+1)*132+n], h, l);
            sEh[n*36+kp]=h; sEl[n*36+kp]=l;
        }
        if(tid<64){
            #pragma unroll
            for(int kp=0;kp<32;kp++){
                uint32_t h=sAh[tid*36+kp], l=sAl[tid*36+kp];
                rsum += unpk(h,l,0)+unpk(h,l,1);
            }
        }
        __syncthreads();
        gemm3<2,36,36,4>(sAh,sAl,sEh,sEl,wm,wn,lane,acc);
        __syncthreads();
    }
    FOREACH(2,
        *(float2*)&g_s0[((long)bb*NN+rl)*DD+col] =
            make_float2(acc[f][2*h], acc[f][2*h+1]);
    )
    if(tid<64) g_rs[bb*NN+tid]=rsum;
}

// ---------------- e5 = e0 @ (W^5)^T + c5 ; residual colsums ----------------
__global__ void __launch_bounds__(256) k_e5(const float* __restrict__ E0,
                                            float* __restrict__ outE){
    extern __shared__ uint32_t sm[];
    uint32_t* sXh=sm; uint32_t* sXl=sm+4352;
    const int tid=threadIdx.x, lane=tid&31, wid=tid>>5;
    const int wm=(wid>>2)*32, wn=(wid&3)*32;
    const long rb=(long)blockIdx.x*64;
    split_tile<64>(sXh,sXl,E0+rb*DD,tid);
    __syncthreads();
    float acc[8][4]={};
    gemm3g<2,8>(sXh,sXl,g_W5pk[0],g_W5pk[1],wm,wn,lane,acc);
    FOREACH(2,
        float2 cv=*(const float2*)&g_c5[col];
        *(float2*)&outE[(rb+rl)*DD+col] =
            make_float2(acc[f][2*h]+cv.x, acc[f][2*h+1]+cv.y);
    )
    if(tid<DD){
        float s=0.f; int w=tid>>1, hh=tid&1;
        #pragma unroll 16
        for(int r=0;r<64;r++) s += unpk(sXh[r*LDP+w], sXl[r*LDP+w], hh);
        g_respart[blockIdx.x*DD+tid]=s;
    }
}
__global__ void __launch_bounds__(128) k_residual(const float* __restrict__ p0){
    int bb=blockIdx.x, d=threadIdx.x;
    float s=0.f;
    #pragma unroll
    for(int c=0;c<16;c++) s += g_respart[(bb*16+c)*DD+d];
    for(int n=0;n<NN;n++) s += p0[((long)bb*NN+n)*DD+d];
    g_resid[bb*DD+d]=s;
}

// ---------------- persistent fused GRU (5 steps) + attention epilogue ----------------
__global__ void __launch_bounds__(256) k_gru(
    const float* __restrict__ p0in,
    const float* __restrict__ bl, const float* __restrict__ br,
    const float* __restrict__ bz, const float* __restrict__ bh,
    const float* __restrict__ bo, const float* __restrict__ ba1,
    const float* __restrict__ Wa2, const float* __restrict__ ba2,
    float* __restrict__ outO)
{
    extern __shared__ uint32_t sm[];
    uint32_t* T1h=sm;        uint32_t* T1l=sm+8704;
    uint32_t* Tph=sm+17408;  uint32_t* Tpl=sm+26112;
    const int tid=threadIdx.x, lane=tid&31, wid=tid>>5;
    const int wm=(wid>>2)*64, wn=(wid&3)*32;
    const long rb=(long)blockIdx.x*128;

    split_tile<128>(T1h,T1l,g_s0+rb*DD,tid);
    float pr[16][4], zf[16][4], acc[16][4], rs8[8];
    FOREACH(4,
        float2 pv=*(const float2*)&p0in[(rb+rl)*DD+col];
        pr[f][2*h]=pv.x; pr[f][2*h+1]=pv.y;
        if(ni==0) rs8[mi*2+h]=g_rs[rb+rl];
    )
    FOREACH(4,
        uint32_t hh; uint32_t ll; split2(pr[f][2*h],pr[f][2*h+1],hh,ll);
        Tph[rl*LDP+(col>>1)]=hh; Tpl[rl*LDP+(col>>1)]=ll;
    )
    __syncthreads();

#define G3G(X, id, A) gemm3g<4,8>(X##h, X##l, g_Wpk[id][0], g_Wpk[id][1], wm, wn, lane, A)

    for(int t=0;t<5;t++){
        // a = s@Wl^T + rs*bl -> T1
        ZERO(acc,16); G3G(T1,0,acc);
        __syncthreads();
        FOREACH(4,
            float2 bv=*(const float2*)&bl[col];
            float v0=acc[f][2*h]+rs8[mi*2+h]*bv.x;
            float v1=acc[f][2*h+1]+rs8[mi*2+h]*bv.y;
            uint32_t hh; uint32_t ll; split2(v0,v1,hh,ll);
            T1h[rl*LDP+(col>>1)]=hh; T1l[rl*LDP+(col>>1)]=ll;
        )
        __syncthreads();
        // z
        ZERO(zf,16); G3G(T1,1,zf); G3G(Tp,2,zf);
        FOREACH(4,
            float2 bv=*(const float2*)&bz[col];
            zf[f][2*h]=sigf(zf[f][2*h]+bv.x); zf[f][2*h+1]=sigf(zf[f][2*h+1]+bv.y);
        )
        // r -> Tp = split(r*p)
        ZERO(acc,16); G3G(T1,3,acc); G3G(Tp,4,acc);
        __syncthreads();
        FOREACH(4,
            float2 bv=*(const float2*)&br[col];
            float r0=sigf(acc[f][2*h]+bv.x);
            float r1=sigf(acc[f][2*h+1]+bv.y);
            uint32_t hh; uint32_t ll; split2(r0*pr[f][2*h], r1*pr[f][2*h+1], hh, ll);
            Tph[rl*LDP+(col>>1)]=hh; Tpl[rl*LDP+(col>>1)]=ll;
        )
        __syncthreads();
        // h, p update
        ZERO(acc,16); G3G(T1,5,acc); G3G(Tp,6,acc);
        FOREACH(4,
            float2 bv=*(const float2*)&bh[col];
            float h0=tanhf(acc[f][2*h]+bv.x);
            float h1=tanhf(acc[f][2*h+1]+bv.y);
            pr[f][2*h]  =(1.f-zf[f][2*h])*pr[f][2*h]+zf[f][2*h]*h0;
            pr[f][2*h+1]=(1.f-zf[f][2*h+1])*pr[f][2*h+1]+zf[f][2*h+1]*h1;
        )
        __syncthreads();
        FOREACH(4,
            uint32_t hh; uint32_t ll; split2(pr[f][2*h],pr[f][2*h+1],hh,ll);
            Tph[rl*LDP+(col>>1)]=hh; Tpl[rl*LDP+(col>>1)]=ll;
        )
        __syncthreads();
    }
    // out = tanh(p@Wo^T+bo)
    ZERO(acc,16); G3G(Tp,7,acc);
    FOREACH(4,
        float2 bv=*(const float2*)&bo[col];
        *(float2*)&outO[(rb+rl)*DD+col] =
            make_float2(tanhf(acc[f][2*h]+bv.x), tanhf(acc[f][2*h+1]+bv.y));
    )
    // attention logits
    ZERO(acc,16); G3G(Tp,8,acc);
    __syncthreads();
    float* sT=(float*)sm;   // reuse T1 region: [128][132] fp32
    FOREACH(4,
        float2 bv=*(const float2*)&ba1[col];
        sT[rl*132+col]  =tanhf(acc[f][2*h]+bv.x);
        sT[rl*132+col+1]=tanhf(acc[f][2*h+1]+bv.y);
    )
    __syncthreads();
    if(tid<128){
        float d=0.f;
        #pragma unroll 16
        for(int c=0;c<DD;c++) d += sT[tid*132+c]*Wa2[c];
        g_attl[rb+tid]=d+ba2[0];
    }
}

// ---------------- final: softmax, weighted sum, residual, relu ----------------
__global__ void __launch_bounds__(128) k_final(const float* __restrict__ outO,
                                               float* __restrict__ res){
    __shared__ float sl[64], se[64];
    const int bb=blockIdx.x, tid=threadIdx.x;
    if(tid<64) sl[tid]=g_attl[bb*NN+tid];
    __syncthreads();
    float mx=-1e30f;
    #pragma unroll
    for(int n=0;n<64;n++) mx=fmaxf(mx,sl[n]);
    if(tid<64) se[tid]=__expf(sl[tid]-mx);
    __syncthreads();
    float sum=0.f;
    #pragma unroll
    for(int n=0;n<64;n++) sum+=se[n];
    const float* ob=outO+(long)bb*NN*DD+tid;
    float ws=0.f;
    #pragma unroll 8
    for(int n=0;n<64;n++) ws+=se[n]*ob[n*DD];
    float g=tanhf(ws/sum);
    float rr=g+g_resid[bb*DD+tid]*(1.f/1088.f);
    res[bb*DD+tid]=fmaxf(rr,0.f);
}

// ---------------- launch ----------------
extern "C" void kernel_launch(void* const* d_in, const int* in_sizes, int n_in,
                              void* d_out, int out_size)
{
    const float* in_prop=(const float*)d_in[0];
    const float* in_edge=(const float*)d_in[1];
    const float* in_A  =(const float*)d_in[2];
    const float* Wl =(const float*)d_in[3];
    const float* bl =(const float*)d_in[4];
    const float* Wr =(const float*)d_in[5];
    const float* br =(const float*)d_in[6];
    const float* Wz =(const float*)d_in[7];
    const float* bz =(const float*)d_in[8];
    const float* Wh =(const float*)d_in[9];
    const float* bh =(const float*)d_in[10];
    const float* Wa1=(const float*)d_in[11];
    const float* ba1=(const float*)d_in[12];
    const float* Wa2=(const float*)d_in[13];
    const float* ba2=(const float*)d_in[14];
    const float* Wo =(const float*)d_in[15];
    const float* bo =(const float*)d_in[16];

    float* out =(float*)d_out;
    float* res =out;
    float* outO=out+B*DD;
    float* outE=out+B*DD+(long)BN*DD;

    const int SA_SM=(DD*DD+1024)*4, SB_SM=(2*DD*DD+1024)*4;
    const int S0_SM=22272*4, E5_SM=8704*4, GR_SM=34816*4;
    cudaFuncSetAttribute(k_sqmmA, cudaFuncAttributeMaxDynamicSharedMemorySize, SA_SM);
    cudaFuncSetAttribute(k_sqmmB, cudaFuncAttributeMaxDynamicSharedMemorySize, SB_SM);
    cudaFuncSetAttribute(k_s0,    cudaFuncAttributeMaxDynamicSharedMemorySize, S0_SM);
    cudaFuncSetAttribute(k_e5,    cudaFuncAttributeMaxDynamicSharedMemorySize, E5_SM);
    cudaFuncSetAttribute(k_gru,   cudaFuncAttributeMaxDynamicSharedMemorySize, GR_SM);

    k_prep<<<10,256>>>(Wl,Wr,Wz,Wh,Wo,Wa1,bl);
    k_sqmmA<<<16,1024,SA_SM>>>(Wl);
    k_sqmmB<<<16,1024,SB_SM>>>(Wl);
    k_s0<<<B,256,S0_SM>>>(in_A,in_edge);
    k_e5<<<BE/64,256,E5_SM>>>(in_edge,outE);
    k_gru<<<BN/128,256,GR_SM>>>(in_prop,bl,br,bz,bh,bo,ba1,Wa2,ba2,outO);
    k_residual<<<B,128>>>(in_prop);
    k_final<<<B,128>>>(outO,res);
}

// round 15
// speedup vs baseline: 1.8240x; 1.8240x over previous
#include <cuda_runtime.h>
#include <cuda_bf16.h>
#include <cstdint>

#define B 512
#define NN 64
#define NE 1024
#define DD 128
#define BN (B*NN)
#define BE (B*NE)
#define LDP 68

__device__ __align__(16) uint32_t g_Wpk[9][2][DD*64];
__device__ __align__(16) uint32_t g_W5pk[2][DD*64];
__device__ __align__(16) float g_P0[DD*DD];
__device__ __align__(16) float g_c5[DD];
__device__ __align__(16) float g_s0[BN*DD];
__device__ float g_rs[BN];
__device__ float g_respart[(BE/64)*DD];
__device__ float g_resid[B*DD];
__device__ float g_attl[BN];

__device__ __forceinline__ float sigf(float x){ return 1.f/(1.f+__expf(-x)); }
__device__ __forceinline__ void split2(float x0, float x1, uint32_t& hi, uint32_t& lo){
    __nv_bfloat162 h = __floats2bfloat162_rn(x0, x1);
    __nv_bfloat162 l = __floats2bfloat162_rn(x0-__low2float(h), x1-__high2float(h));
    hi = *reinterpret_cast<uint32_t*>(&h);
    lo = *reinterpret_cast<uint32_t*>(&l);
}
__device__ __forceinline__ float unpk(uint32_t h, uint32_t l, int half){
    __nv_bfloat162 hb = *reinterpret_cast<__nv_bfloat162*>(&h);
    __nv_bfloat162 lb = *reinterpret_cast<__nv_bfloat162*>(&l);
    return half ? (__high2float(hb)+__high2float(lb)) : (__low2float(hb)+__low2float(lb));
}
__device__ __forceinline__ void mma16(float c[4], const uint32_t a[4], const uint32_t b[2]){
    asm volatile("mma.sync.aligned.m16n8k16.row.col.f32.bf16.bf16.f32 "
        "{%0,%1,%2,%3}, {%4,%5,%6,%7}, {%8,%9}, {%0,%1,%2,%3};"
        : "+f"(c[0]),"+f"(c[1]),"+f"(c[2]),"+f"(c[3])
        : "r"(a[0]),"r"(a[1]),"r"(a[2]),"r"(a[3]),"r"(b[0]),"r"(b[1]));
}
template<int MI,int LDA,int LDB,int KS>
__device__ __forceinline__ void gemm3(const uint32_t* Ah, const uint32_t* Al,
                                      const uint32_t* Bh, const uint32_t* Bl,
                                      int wm, int wn, int lane, float (*acc)[4]){
    #pragma unroll
    for(int ks=0;ks<KS;ks++){
        const int kp = ks*8 + (lane&3);
        uint32_t ah[MI][4], al[MI][4];
        #pragma unroll
        for(int mi=0;mi<MI;mi++){
            int ro = (wm+16*mi+(lane>>2))*LDA + kp;
            ah[mi][0]=Ah[ro]; ah[mi][1]=Ah[ro+8*LDA]; ah[mi][2]=Ah[ro+4]; ah[mi][3]=Ah[ro+8*LDA+4];
            al[mi][0]=Al[ro]; al[mi][1]=Al[ro+8*LDA]; al[mi][2]=Al[ro+4]; al[mi][3]=Al[ro+8*LDA+4];
        }
        #pragma unroll
        for(int ni=0;ni<4;ni++){
            int ro = (wn+8*ni+(lane>>2))*LDB + kp;
            uint32_t bh[2]={Bh[ro],Bh[ro+4]}, bl_[2]={Bl[ro],Bl[ro+4]};
            #pragma unroll
            for(int mi=0;mi<MI;mi++){
                mma16(acc[mi*4+ni], ah[mi], bh);
                mma16(acc[mi*4+ni], al[mi], bh);
                mma16(acc[mi*4+ni], ah[mi], bl_);
            }
        }
    }
}
#define FOREACH(MI_, ...) \
  {_Pragma("unroll") for(int mi=0;mi<MI_;mi++) \
  _Pragma("unroll") for(int h=0;h<2;h++){ \
    int rl=wm+16*mi+8*h+(lane>>2); (void)rl; \
    _Pragma("unroll") for(int ni=0;ni<4;ni++){ \
      int f=mi*4+ni; int col=wn+8*ni+(lane&3)*2; (void)f; (void)col; __VA_ARGS__ } }}
#define ZERO(A,NF) {_Pragma("unroll") for(int f_=0;f_<NF;f_++){A[f_][0]=A[f_][1]=A[f_][2]=A[f_][3]=0.f;}}

template<int R>
__device__ __forceinline__ void split_tile(uint32_t* dh, uint32_t* dl,
                                           const float* __restrict__ src, int tid){
    #pragma unroll
    for(int i=0;i<R/8;i++){
        int idx=i*256+tid; int r=idx>>5, c=idx&31;
        float4 v=*(const float4*)(src+(long)r*DD+c*4);
        uint32_t h0,l0,h1,l1; split2(v.x,v.y,h0,l0); split2(v.z,v.w,h1,l1);
        dh[r*LDP+c*2]=h0; dh[r*LDP+c*2+1]=h1;
        dl[r*LDP+c*2]=l0; dl[r*LDP+c*2+1]=l1;
    }
}
__device__ __forceinline__ void copy_slab68(uint32_t* dh, uint32_t* dl,
        const uint32_t* __restrict__ sh, const uint32_t* __restrict__ sl, int tid){
    #pragma unroll
    for(int i=0;i<8;i++){
        int idx=i*256+tid; int r=idx>>4, c4=(idx&15)*4;
        *(uint4*)(dh+r*LDP+c4) = *(const uint4*)(sh+r*64+c4);
        *(uint4*)(dl+r*LDP+c4) = *(const uint4*)(sl+r*64+c4);
    }
}
// copy one K-half of a packed slab [128][64] -> smem [128][36]
__device__ __forceinline__ void copy_half(uint32_t* dh, uint32_t* dl,
        const uint32_t* __restrict__ sh, const uint32_t* __restrict__ sl,
        int half, int tid){
    #pragma unroll
    for(int i=0;i<4;i++){
        int idx=i*256+tid; int n=idx>>3, q=idx&7;
        *(uint4*)(dh+n*36+q*4) = *(const uint4*)(sh+n*64+half*32+q*4);
        *(uint4*)(dl+n*36+q*4) = *(const uint4*)(sl+n*64+half*32+q*4);
    }
}

// ---- setup ----
__global__ void __launch_bounds__(256) k_prep(
    const float* __restrict__ Wl, const float* __restrict__ Wr,
    const float* __restrict__ Wz, const float* __restrict__ Wh,
    const float* __restrict__ Wo, const float* __restrict__ Wa1,
    const float* __restrict__ bl){
    __shared__ float c[DD];
    int bi=blockIdx.x, tid=threadIdx.x;
    if(bi==9){
        if(tid<DD) c[tid]=0.f;
        __syncthreads();
        for(int t=0;t<5;t++){
            float a=0.f;
            if(tid<DD){
                a=bl[tid];
                const float4* W4=(const float4*)(Wl+tid*DD);
                #pragma unroll 8
                for(int k=0;k<32;k++){ float4 w=W4[k];
                    a += w.x*c[4*k]+w.y*c[4*k+1]+w.z*c[4*k+2]+w.w*c[4*k+3]; }
            }
            __syncthreads(); if(tid<DD) c[tid]=a; __syncthreads();
        }
        if(tid<DD) g_c5[tid]=c[tid];
        return;
    }
    const float* S[9]={Wl,Wz,Wz,Wr,Wr,Wh,Wh,Wo,Wa1};
    const int ST[9]={128,256,256,256,256,256,256,128,128};
    const int OF[9]={0,0,128,0,128,0,128,0,0};
    const float* src=S[bi]; int strd=ST[bi], off=OF[bi];
    for(int idx=tid; idx<DD*64; idx+=256){
        int r=idx>>6, kp=idx&63;
        const float* p=src+(long)r*strd+off+2*kp;
        uint32_t h,l; split2(p[0],p[1],h,l);
        g_Wpk[bi][0][idx]=h; g_Wpk[bi][1][idx]=l;
    }
}
__global__ void __launch_bounds__(1024) k_sqmmA(const float* __restrict__ Wl){
    extern __shared__ float s[];
    float* sY=s; float* sX=s+DD*DD;
    int tid=threadIdx.x;
    #pragma unroll
    for(int j=0;j<16;j++) sY[j*1024+tid]=Wl[j*1024+tid];
    int r0=blockIdx.x*8;
    sX[tid]=Wl[r0*DD+tid];
    __syncthreads();
    int ty=tid>>7, o=tid&127;
    float acc=0.f;
    #pragma unroll 16
    for(int m=0;m<DD;m++) acc += sX[ty*DD+m]*sY[m*DD+o];
    g_P0[(r0+ty)*DD+o]=acc;
}
__global__ void __launch_bounds__(1024) k_sqmmB(const float* __restrict__ Wl){
    extern __shared__ float s[];
    float* sW2=s; float* sW=s+DD*DD; float* sA=s+2*DD*DD;
    int tid=threadIdx.x;
    #pragma unroll
    for(int j=0;j<16;j++){ sW2[j*1024+tid]=g_P0[j*1024+tid]; sW[j*1024+tid]=Wl[j*1024+tid]; }
    __syncthreads();
    int r=tid>>7, o=tid&127, R=blockIdx.x*8+r;
    float a=0.f;
    #pragma unroll 16
    for(int k=0;k<DD;k++) a += sW2[R*DD+k]*sW2[k*DD+o];
    sA[tid]=a;
    __syncthreads();
    float b=0.f;
    #pragma unroll 16
    for(int k=0;k<DD;k++) b += sA[r*DD+k]*sW[k*DD+o];
    __syncthreads();
    sA[tid]=b;
    __syncthreads();
    if(tid<512){
        int rr=tid>>6, kp=tid&63;
        uint32_t h,l; split2(sA[rr*DD+2*kp], sA[rr*DD+2*kp+1], h, l);
        g_W5pk[0][(blockIdx.x*8+rr)*64+kp]=h;
        g_W5pk[1][(blockIdx.x*8+rr)*64+kp]=l;
    }
}

// ---- e5 = e0 @ (W^5)^T + c5 ; residual colsums (profiled: launch #4) ----
__global__ void __launch_bounds__(256) k_e5(const float* __restrict__ E0,
                                            float* __restrict__ outE){
    extern __shared__ uint32_t sm[];
    uint32_t* sXh=sm; uint32_t* sXl=sm+4352;
    uint32_t* sWh=sm+8704; uint32_t* sWl=sm+17408;
    const int tid=threadIdx.x, lane=tid&31, wid=tid>>5;
    const int wm=(wid>>2)*32, wn=(wid&3)*32;
    const long rb=(long)blockIdx.x*64;
    split_tile<64>(sXh,sXl,E0+rb*DD,tid);
    copy_slab68(sWh,sWl,g_W5pk[0],g_W5pk[1],tid);
    __syncthreads();
    float acc[8][4]={};
    gemm3<2,LDP,LDP,8>(sXh,sXl,sWh,sWl,wm,wn,lane,acc);
    FOREACH(2,
        float2 cv=*(const float2*)&g_c5[col];
        *(float2*)&outE[(rb+rl)*DD+col] =
            make_float2(acc[f][2*h]+cv.x, acc[f][2*h+1]+cv.y);
    )
    if(tid<DD){
        float s=0.f; int w=tid>>1, hh=tid&1;
        #pragma unroll 16
        for(int r=0;r<64;r++) s += unpk(sXh[r*LDP+w], sXl[r*LDP+w], hh);
        g_respart[blockIdx.x*DD+tid]=s;
    }
}

// ---- s0 = A @ e0 + rowsum(A) ----
__global__ void __launch_bounds__(256) k_s0(const float* __restrict__ A,
                                            const float* __restrict__ E0){
    extern __shared__ uint32_t sm[];
    float*    sF  =(float*)sm;
    uint32_t* sAh = sm+8448;
    uint32_t* sAl = sm+10752;
    uint32_t* sEh = sm+13056;
    uint32_t* sEl = sm+17664;
    const int tid=threadIdx.x, lane=tid&31, wid=tid>>5;
    const int wm=(wid>>2)*32, wn=(wid&3)*32;
    const int g=lane>>2, q=lane&3;
    const int bb=blockIdx.x;
    const float* Ab=A +(long)bb*NN*NE;
    const float* Eb=E0+(long)bb*NE*DD;
    float acc[8][4]={}; float rsum=0.f;
    for(int kc=0;kc<16;kc++){
        const int kb=kc*64;
        #pragma unroll
        for(int i=0;i<4;i++){
            int idx=i*256+tid; int r=idx>>4, cq=idx&15;
            float4 v=*(const float4*)(Ab+(long)r*NE+kb+cq*4);
            uint32_t h0,l0,h1,l1; split2(v.x,v.y,h0,l0); split2(v.z,v.w,h1,l1);
            sAh[r*36+cq*2]=h0; sAh[r*36+cq*2+1]=h1;
            sAl[r*36+cq*2]=l0; sAl[r*36+cq*2+1]=l1;
        }
        #pragma unroll
        for(int i=0;i<8;i++){
            int idx=i*256+tid; int r=idx>>5, c=idx&31;
            *(float4*)(sF+r*132+c*4)=*(const float4*)(Eb+(long)(kb+r)*DD+c*4);
        }
        __syncthreads();
        #pragma unroll
        for(int ii=0;ii<16;ii++){
            int n =(ii&3)*32+(wid&3)*8+g;
            int kp=(ii>>2)*8+(wid>>2)*4+q;
            uint32_t h,l; split2(sF[(2*kp)*132+n], sF[(2*kp+1)*132+n], h, l);
            sEh[n*36+kp]=h; sEl[n*36+kp]=l;
        }
        if(tid<64){
            #pragma unroll
            for(int kp=0;kp<32;kp++){
                uint32_t h=sAh[tid*36+kp], l=sAl[tid*36+kp];
                rsum += unpk(h,l,0)+unpk(h,l,1);
            }
        }
        __syncthreads();
        gemm3<2,36,36,4>(sAh,sAl,sEh,sEl,wm,wn,lane,acc);
        __syncthreads();
    }
    FOREACH(2,
        *(float2*)&g_s0[((long)bb*NN+rl)*DD+col] =
            make_float2(acc[f][2*h], acc[f][2*h+1]);
    )
    if(tid<64) g_rs[bb*NN+tid]=rsum;
}
__global__ void __launch_bounds__(128) k_residual(const float* __restrict__ p0){
    int bb=blockIdx.x, d=threadIdx.x;
    float s=0.f;
    #pragma unroll
    for(int c=0;c<16;c++) s += g_respart[(bb*16+c)*DD+d];
    for(int n=0;n<NN;n++) s += p0[((long)bb*NN+n)*DD+d];
    g_resid[bb*DD+d]=s;
}

// ---- persistent fused GRU: 64 rows/block, half-K slabs, 2 blocks/SM ----
__global__ void __launch_bounds__(256) k_gru(
    const float* __restrict__ p0in,
    const float* __restrict__ bl, const float* __restrict__ br,
    const float* __restrict__ bz, const float* __restrict__ bh,
    const float* __restrict__ bo, const float* __restrict__ ba1,
    const float* __restrict__ Wa2, const float* __restrict__ ba2,
    float* __restrict__ outO)
{
    extern __shared__ uint32_t sm[];
    uint32_t* T1h=sm;        uint32_t* T1l=sm+4352;
    uint32_t* Tph=sm+8704;   uint32_t* Tpl=sm+13056;
    uint32_t* WBh=sm+17408;  uint32_t* WBl=sm+22016;   // [128][36] pair
    const int tid=threadIdx.x, lane=tid&31, wid=tid>>5;
    const int wm=(wid>>2)*32, wn=(wid&3)*32;
    const long rb=(long)blockIdx.x*64;

    split_tile<64>(T1h,T1l,g_s0+rb*DD,tid);
    float pr[8][4], zf[8][4], acc[8][4], rs4[4];
    FOREACH(2,
        float2 pv=*(const float2*)&p0in[(rb+rl)*DD+col];
        pr[f][2*h]=pv.x; pr[f][2*h+1]=pv.y;
        if(ni==0) rs4[mi*2+h]=g_rs[rb+rl];
    )
    FOREACH(2,
        uint32_t hh; uint32_t ll; split2(pr[f][2*h],pr[f][2*h+1],hh,ll);
        Tph[rl*LDP+(col>>1)]=hh; Tpl[rl*LDP+(col>>1)]=ll;
    )
    __syncthreads();

    // one half-slab round: sync, copy, sync, gemm(KS=4) on A tile (+32 words for K-half 1)
#define ROUND(sid, hf, Xh, Xl, A) { \
    __syncthreads(); \
    copy_half(WBh,WBl,g_Wpk[sid][0],g_Wpk[sid][1],hf,tid); \
    __syncthreads(); \
    gemm3<2,LDP,36,4>(Xh+32*hf, Xl+32*hf, WBh, WBl, wm, wn, lane, A); }
#define GEMM1(sid, Xh, Xl, A) ROUND(sid,0,Xh,Xl,A) ROUND(sid,1,Xh,Xl,A)

    for(int t=0;t<5;t++){
        // a = s@Wl^T + rs*bl -> T1
        ZERO(acc,8); GEMM1(0, T1h, T1l, acc);
        __syncthreads();
        FOREACH(2,
            float2 bv=*(const float2*)&bl[col];
            float v0=acc[f][2*h]+rs4[mi*2+h]*bv.x;
            float v1=acc[f][2*h+1]+rs4[mi*2+h]*bv.y;
            uint32_t hh; uint32_t ll; split2(v0,v1,hh,ll);
            T1h[rl*LDP+(col>>1)]=hh; T1l[rl*LDP+(col>>1)]=ll;
        )
        // z
        ZERO(zf,8); GEMM1(1, T1h, T1l, zf); GEMM1(2, Tph, Tpl, zf);
        FOREACH(2,
            float2 bv=*(const float2*)&bz[col];
            zf[f][2*h]=sigf(zf[f][2*h]+bv.x); zf[f][2*h+1]=sigf(zf[f][2*h+1]+bv.y);
        )
        // r -> Tp = split(r*p)
        ZERO(acc,8); GEMM1(3, T1h, T1l, acc); GEMM1(4, Tph, Tpl, acc);
        __syncthreads();
        FOREACH(2,
            float2 bv=*(const float2*)&br[col];
            float r0=sigf(acc[f][2*h]+bv.x);
            float r1=sigf(acc[f][2*h+1]+bv.y);
            uint32_t hh; uint32_t ll; split2(r0*pr[f][2*h], r1*pr[f][2*h+1], hh, ll);
            Tph[rl*LDP+(col>>1)]=hh; Tpl[rl*LDP+(col>>1)]=ll;
        )
        // h, p update
        ZERO(acc,8); GEMM1(5, T1h, T1l, acc); GEMM1(6, Tph, Tpl, acc);
        FOREACH(2,
            float2 bv=*(const float2*)&bh[col];
            float h0=tanhf(acc[f][2*h]+bv.x);
            float h1=tanhf(acc[f][2*h+1]+bv.y);
            pr[f][2*h]  =(1.f-zf[f][2*h])*pr[f][2*h]+zf[f][2*h]*h0;
            pr[f][2*h+1]=(1.f-zf[f][2*h+1])*pr[f][2*h+1]+zf[f][2*h+1]*h1;
        )
        __syncthreads();
        FOREACH(2,
            uint32_t hh; uint32_t ll; split2(pr[f][2*h],pr[f][2*h+1],hh,ll);
            Tph[rl*LDP+(col>>1)]=hh; Tpl[rl*LDP+(col>>1)]=ll;
        )
    }
    // out = tanh(p@Wo^T+bo)
    ZERO(acc,8); GEMM1(7, Tph, Tpl, acc);
    FOREACH(2,
        float2 bv=*(const float2*)&bo[col];
        *(float2*)&outO[(rb+rl)*DD+col] =
            make_float2(tanhf(acc[f][2*h]+bv.x), tanhf(acc[f][2*h+1]+bv.y));
    )
    // attention logits
    ZERO(acc,8); GEMM1(8, Tph, Tpl, acc);
    __syncthreads();
    float* sT=(float*)sm;   // reuse T1 region: [64][132] fp32
    FOREACH(2,
        float2 bv=*(const float2*)&ba1[col];
        sT[rl*132+col]  =tanhf(acc[f][2*h]+bv.x);
        sT[rl*132+col+1]=tanhf(acc[f][2*h+1]+bv.y);
    )
    __syncthreads();
    if(tid<64){
        float d=0.f;
        #pragma unroll 16
        for(int c=0;c<DD;c++) d += sT[tid*132+c]*Wa2[c];
        g_attl[rb+tid]=d+ba2[0];
    }
}

// ---- final: softmax, weighted sum, residual, relu ----
__global__ void __launch_bounds__(128) k_final(const float* __restrict__ outO,
                                               float* __restrict__ res){
    __shared__ float sl[64], se[64];
    const int bb=blockIdx.x, tid=threadIdx.x;
    if(tid<64) sl[tid]=g_attl[bb*NN+tid];
    __syncthreads();
    float mx=-1e30f;
    #pragma unroll
    for(int n=0;n<64;n++) mx=fmaxf(mx,sl[n]);
    if(tid<64) se[tid]=__expf(sl[tid]-mx);
    __syncthreads();
    float sum=0.f;
    #pragma unroll
    for(int n=0;n<64;n++) sum+=se[n];
    const float* ob=outO+(long)bb*NN*DD+tid;
    float ws=0.f;
    #pragma unroll 8
    for(int n=0;n<64;n++) ws+=se[n]*ob[n*DD];
    float g=tanhf(ws/sum);
    float rr=g+g_resid[bb*DD+tid]*(1.f/1088.f);
    res[bb*DD+tid]=fmaxf(rr,0.f);
}

// ---- launch ----
extern "C" void kernel_launch(void* const* d_in, const int* in_sizes, int n_in,
                              void* d_out, int out_size)
{
    const float* in_prop=(const float*)d_in[0];
    const float* in_edge=(const float*)d_in[1];
    const float* in_A  =(const float*)d_in[2];
    const float* Wl =(const float*)d_in[3];
    const float* bl =(const float*)d_in[4];
    const float* Wr =(const float*)d_in[5];
    const float* br =(const float*)d_in[6];
    const float* Wz =(const float*)d_in[7];
    const float* bz =(const float*)d_in[8];
    const float* Wh =(const float*)d_in[9];
    const float* bh =(const float*)d_in[10];
    const float* Wa1=(const float*)d_in[11];
    const float* ba1=(const float*)d_in[12];
    const float* Wa2=(const float*)d_in[13];
    const float* ba2=(const float*)d_in[14];
    const float* Wo =(const float*)d_in[15];
    const float* bo =(const float*)d_in[16];

    float* out =(float*)d_out;
    float* res =out;
    float* outO=out+B*DD;
    float* outE=out+B*DD+(long)BN*DD;

    const int SA_SM=(DD*DD+1024)*4, SB_SM=(2*DD*DD+1024)*4;
    const int S0_SM=22272*4, E5_SM=26112*4, GR_SM=26624*4;
    cudaFuncSetAttribute(k_sqmmA, cudaFuncAttributeMaxDynamicSharedMemorySize, SA_SM);
    cudaFuncSetAttribute(k_sqmmB, cudaFuncAttributeMaxDynamicSharedMemorySize, SB_SM);
    cudaFuncSetAttribute(k_s0,    cudaFuncAttributeMaxDynamicSharedMemorySize, S0_SM);
    cudaFuncSetAttribute(k_e5,    cudaFuncAttributeMaxDynamicSharedMemorySize, E5_SM);
    cudaFuncSetAttribute(k_gru,   cudaFuncAttributeMaxDynamicSharedMemorySize, GR_SM);

    k_prep<<<10,256>>>(Wl,Wr,Wz,Wh,Wo,Wa1,bl);
    k_sqmmA<<<16,1024,SA_SM>>>(Wl);
    k_sqmmB<<<16,1024,SB_SM>>>(Wl);
    k_e5<<<BE/64,256,E5_SM>>>(in_edge,outE);
    k_s0<<<B,256,S0_SM>>>(in_A,in_edge);
    k_gru<<<BN/64,256,GR_SM>>>(in_prop,bl,br,bz,bh,bo,ba1,Wa2,ba2,outO);
    k_residual<<<B,128>>>(in_prop);
    k_final<<<B,128>>>(outO,res);
}

// round 16
// speedup vs baseline: 1.8565x; 1.0178x over previous
#include <cuda_runtime.h>
#include <cuda_bf16.h>
#include <cstdint>

#define B 512
#define NN 64
#define NE 1024
#define DD 128
#define BN (B*NN)
#define BE (B*NE)
#define LDP 68

__device__ __align__(16) uint32_t g_Wpk[9][2][DD*64];
__device__ __align__(16) uint32_t g_W5pk[2][DD*64];
__device__ __align__(16) float g_P0[DD*DD];
__device__ __align__(16) float g_c5[DD];
__device__ __align__(16) float g_s0[BN*DD];
__device__ float g_rs[BN];
__device__ float g_respart[(BE/64)*DD];
__device__ float g_resid[B*DD];
__device__ float g_attl[BN];

__device__ __forceinline__ float sigf(float x){ return 1.f/(1.f+__expf(-x)); }
__device__ __forceinline__ void split2(float x0, float x1, uint32_t& hi, uint32_t& lo){
    __nv_bfloat162 h = __floats2bfloat162_rn(x0, x1);
    __nv_bfloat162 l = __floats2bfloat162_rn(x0-__low2float(h), x1-__high2float(h));
    hi = *reinterpret_cast<uint32_t*>(&h);
    lo = *reinterpret_cast<uint32_t*>(&l);
}
__device__ __forceinline__ float unpk(uint32_t h, uint32_t l, int half){
    __nv_bfloat162 hb = *reinterpret_cast<__nv_bfloat162*>(&h);
    __nv_bfloat162 lb = *reinterpret_cast<__nv_bfloat162*>(&l);
    return half ? (__high2float(hb)+__high2float(lb)) : (__low2float(hb)+__low2float(lb));
}
__device__ __forceinline__ uint32_t smem_u32(const void* p){
    uint32_t a; asm("{ .reg .u64 t; cvta.to.shared.u64 t, %1; cvt.u32.u64 %0, t; }":"=r"(a):"l"(p)); return a;
}
__device__ __forceinline__ void mma16(float c[4], const uint32_t a[4], const uint32_t b[2]){
    asm volatile("mma.sync.aligned.m16n8k16.row.col.f32.bf16.bf16.f32 "
        "{%0,%1,%2,%3}, {%4,%5,%6,%7}, {%8,%9}, {%0,%1,%2,%3};"
        : "+f"(c[0]),"+f"(c[1]),"+f"(c[2]),"+f"(c[3])
        : "r"(a[0]),"r"(a[1]),"r"(a[2]),"r"(a[3]),"r"(b[0]),"r"(b[1]));
}
__device__ __forceinline__ void ldm4(uint32_t r[4], uint32_t addr){
    asm volatile("ldmatrix.sync.aligned.m8n8.x4.shared.b16 {%0,%1,%2,%3}, [%4];"
        : "=r"(r[0]),"=r"(r[1]),"=r"(r[2]),"=r"(r[3]) : "r"(addr));
}

// 3-term split GEMM with ldmatrix fragment loads.
// A [m][kp] ld LDA (hi/lo), B [n][kp] ld LDB (hi/lo). NI=4 fixed.
template<int MI,int LDA,int LDB,int KS>
__device__ __forceinline__ void gemm3(const uint32_t* Ah_, const uint32_t* Al_,
                                      const uint32_t* Bh_, const uint32_t* Bl_,
                                      int wm, int wn, int lane, float (*acc)[4]){
    const uint32_t aAh=smem_u32(Ah_), aAl=smem_u32(Al_);
    const uint32_t aBh=smem_u32(Bh_), aBl=smem_u32(Bl_);
    const int quad=lane>>3, rw=lane&7;
    // A: matrices {r0-7@k0, r8-15@k0, r0-7@+4w, r8-15@+4w}
    const uint32_t aoff = (uint32_t)(((quad&1)*8 + rw)*LDA + (quad>>1)*4)*4u;
    // B: matrices {n0-7@k0, n0-7@+4w, n8-15@k0, n8-15@+4w}
    const uint32_t boff = (uint32_t)(((quad>>1)*8 + rw)*LDB + (quad&1)*4)*4u;
    #pragma unroll
    for(int ks=0;ks<KS;ks++){
        const uint32_t kb = (uint32_t)(ks*8*4);
        uint32_t ah[MI][4], al[MI][4];
        #pragma unroll
        for(int mi=0;mi<MI;mi++){
            uint32_t base = (uint32_t)((wm+16*mi)*LDA*4) + aoff + kb;
            ldm4(ah[mi], aAh + base);
            ldm4(al[mi], aAl + base);
        }
        uint32_t bh[4][2], bl[4][2];
        #pragma unroll
        for(int np=0;np<2;np++){
            uint32_t base = (uint32_t)((wn+16*np)*LDB*4) + boff + kb;
            uint32_t th[4], tl[4];
            ldm4(th, aBh + base); ldm4(tl, aBl + base);
            bh[2*np][0]=th[0]; bh[2*np][1]=th[1]; bh[2*np+1][0]=th[2]; bh[2*np+1][1]=th[3];
            bl[2*np][0]=tl[0]; bl[2*np][1]=tl[1]; bl[2*np+1][0]=tl[2]; bl[2*np+1][1]=tl[3];
        }
        #pragma unroll
        for(int ni=0;ni<4;ni++)
            #pragma unroll
            for(int mi=0;mi<MI;mi++){
                mma16(acc[mi*4+ni], ah[mi], bh[ni]);
                mma16(acc[mi*4+ni], al[mi], bh[ni]);
                mma16(acc[mi*4+ni], ah[mi], bl[ni]);
            }
    }
}
#define FOREACH(MI_, ...) \
  {_Pragma("unroll") for(int mi=0;mi<MI_;mi++) \
  _Pragma("unroll") for(int h=0;h<2;h++){ \
    int rl=wm+16*mi+8*h+(lane>>2); (void)rl; \
    _Pragma("unroll") for(int ni=0;ni<4;ni++){ \
      int f=mi*4+ni; int col=wn+8*ni+(lane&3)*2; (void)f; (void)col; __VA_ARGS__ } }}
#define ZERO(A,NF) {_Pragma("unroll") for(int f_=0;f_<NF;f_++){A[f_][0]=A[f_][1]=A[f_][2]=A[f_][3]=0.f;}}

template<int R>
__device__ __forceinline__ void split_tile(uint32_t* dh, uint32_t* dl,
                                           const float* __restrict__ src, int tid){
    #pragma unroll
    for(int i=0;i<R/8;i++){
        int idx=i*256+tid; int r=idx>>5, c=idx&31;
        float4 v=*(const float4*)(src+(long)r*DD+c*4);
        uint32_t h0,l0,h1,l1; split2(v.x,v.y,h0,l0); split2(v.z,v.w,h1,l1);
        dh[r*LDP+c*2]=h0; dh[r*LDP+c*2+1]=h1;
        dl[r*LDP+c*2]=l0; dl[r*LDP+c*2+1]=l1;
    }
}
__device__ __forceinline__ void copy_slab68(uint32_t* dh, uint32_t* dl,
        const uint32_t* __restrict__ sh, const uint32_t* __restrict__ sl, int tid){
    #pragma unroll
    for(int i=0;i<8;i++){
        int idx=i*256+tid; int r=idx>>4, c4=(idx&15)*4;
        *(uint4*)(dh+r*LDP+c4) = *(const uint4*)(sh+r*64+c4);
        *(uint4*)(dl+r*LDP+c4) = *(const uint4*)(sl+r*64+c4);
    }
}
__device__ __forceinline__ void copy_half(uint32_t* dh, uint32_t* dl,
        const uint32_t* __restrict__ sh, const uint32_t* __restrict__ sl,
        int half, int tid){
    #pragma unroll
    for(int i=0;i<4;i++){
        int idx=i*256+tid; int n=idx>>3, q=idx&7;
        *(uint4*)(dh+n*36+q*4) = *(const uint4*)(sh+n*64+half*32+q*4);
        *(uint4*)(dl+n*36+q*4) = *(const uint4*)(sl+n*64+half*32+q*4);
    }
}

// ---- setup ----
__global__ void __launch_bounds__(256) k_prep(
    const float* __restrict__ Wl, const float* __restrict__ Wr,
    const float* __restrict__ Wz, const float* __restrict__ Wh,
    const float* __restrict__ Wo, const float* __restrict__ Wa1,
    const float* __restrict__ bl){
    __shared__ float c[DD];
    int bi=blockIdx.x, tid=threadIdx.x;
    if(bi==9){
        if(tid<DD) c[tid]=0.f;
        __syncthreads();
        for(int t=0;t<5;t++){
            float a=0.f;
            if(tid<DD){
                a=bl[tid];
                const float4* W4=(const float4*)(Wl+tid*DD);
                #pragma unroll 8
                for(int k=0;k<32;k++){ float4 w=W4[k];
                    a += w.x*c[4*k]+w.y*c[4*k+1]+w.z*c[4*k+2]+w.w*c[4*k+3]; }
            }
            __syncthreads(); if(tid<DD) c[tid]=a; __syncthreads();
        }
        if(tid<DD) g_c5[tid]=c[tid];
        return;
    }
    const float* S[9]={Wl,Wz,Wz,Wr,Wr,Wh,Wh,Wo,Wa1};
    const int ST[9]={128,256,256,256,256,256,256,128,128};
    const int OF[9]={0,0,128,0,128,0,128,0,0};
    const float* src=S[bi]; int strd=ST[bi], off=OF[bi];
    for(int idx=tid; idx<DD*64; idx+=256){
        int r=idx>>6, kp=idx&63;
        const float* p=src+(long)r*strd+off+2*kp;
        uint32_t h,l; split2(p[0],p[1],h,l);
        g_Wpk[bi][0][idx]=h; g_Wpk[bi][1][idx]=l;
    }
}
__global__ void __launch_bounds__(1024) k_sqmmA(const float* __restrict__ Wl){
    extern __shared__ float s[];
    float* sY=s; float* sX=s+DD*DD;
    int tid=threadIdx.x;
    #pragma unroll
    for(int j=0;j<16;j++) sY[j*1024+tid]=Wl[j*1024+tid];
    int r0=blockIdx.x*8;
    sX[tid]=Wl[r0*DD+tid];
    __syncthreads();
    int ty=tid>>7, o=tid&127;
    float acc=0.f;
    #pragma unroll 16
    for(int m=0;m<DD;m++) acc += sX[ty*DD+m]*sY[m*DD+o];
    g_P0[(r0+ty)*DD+o]=acc;
}
__global__ void __launch_bounds__(1024) k_sqmmB(const float* __restrict__ Wl){
    extern __shared__ float s[];
    float* sW2=s; float* sW=s+DD*DD; float* sA=s+2*DD*DD;
    int tid=threadIdx.x;
    #pragma unroll
    for(int j=0;j<16;j++){ sW2[j*1024+tid]=g_P0[j*1024+tid]; sW[j*1024+tid]=Wl[j*1024+tid]; }
    __syncthreads();
    int r=tid>>7, o=tid&127, R=blockIdx.x*8+r;
    float a=0.f;
    #pragma unroll 16
    for(int k=0;k<DD;k++) a += sW2[R*DD+k]*sW2[k*DD+o];
    sA[tid]=a;
    __syncthreads();
    float b=0.f;
    #pragma unroll 16
    for(int k=0;k<DD;k++) b += sA[r*DD+k]*sW[k*DD+o];
    __syncthreads();
    sA[tid]=b;
    __syncthreads();
    if(tid<512){
        int rr=tid>>6, kp=tid&63;
        uint32_t h,l; split2(sA[rr*DD+2*kp], sA[rr*DD+2*kp+1], h, l);
        g_W5pk[0][(blockIdx.x*8+rr)*64+kp]=h;
        g_W5pk[1][(blockIdx.x*8+rr)*64+kp]=l;
    }
}

// ---- e5 = e0 @ (W^5)^T + c5 ; residual colsums ----
__global__ void __launch_bounds__(256) k_e5(const float* __restrict__ E0,
                                            float* __restrict__ outE){
    extern __shared__ uint32_t sm[];
    uint32_t* sXh=sm; uint32_t* sXl=sm+4352;
    uint32_t* sWh=sm+8704; uint32_t* sWl=sm+17408;
    const int tid=threadIdx.x, lane=tid&31, wid=tid>>5;
    const int wm=(wid>>2)*32, wn=(wid&3)*32;
    const long rb=(long)blockIdx.x*64;
    split_tile<64>(sXh,sXl,E0+rb*DD,tid);
    copy_slab68(sWh,sWl,g_W5pk[0],g_W5pk[1],tid);
    __syncthreads();
    float acc[8][4]={};
    gemm3<2,LDP,LDP,8>(sXh,sXl,sWh,sWl,wm,wn,lane,acc);
    FOREACH(2,
        float2 cv=*(const float2*)&g_c5[col];
        *(float2*)&outE[(rb+rl)*DD+col] =
            make_float2(acc[f][2*h]+cv.x, acc[f][2*h+1]+cv.y);
    )
    if(tid<DD){
        float s=0.f; int w=tid>>1, hh=tid&1;
        #pragma unroll 16
        for(int r=0;r<64;r++) s += unpk(sXh[r*LDP+w], sXl[r*LDP+w], hh);
        g_respart[blockIdx.x*DD+tid]=s;
    }
}

// ---- s0 = A @ e0 + rowsum(A) ----
__global__ void __launch_bounds__(256) k_s0(const float* __restrict__ A,
                                            const float* __restrict__ E0){
    extern __shared__ uint32_t sm[];
    float*    sF  =(float*)sm;
    uint32_t* sAh = sm+8448;
    uint32_t* sAl = sm+10752;
    uint32_t* sEh = sm+13056;
    uint32_t* sEl = sm+17664;
    const int tid=threadIdx.x, lane=tid&31, wid=tid>>5;
    const int wm=(wid>>2)*32, wn=(wid&3)*32;
    const int g=lane>>2, q=lane&3;
    const int bb=blockIdx.x;
    const float* Ab=A +(long)bb*NN*NE;
    const float* Eb=E0+(long)bb*NE*DD;
    float acc[8][4]={}; float rsum=0.f;
    for(int kc=0;kc<16;kc++){
        const int kb=kc*64;
        #pragma unroll
        for(int i=0;i<4;i++){
            int idx=i*256+tid; int r=idx>>4, cq=idx&15;
            float4 v=*(const float4*)(Ab+(long)r*NE+kb+cq*4);
            uint32_t h0,l0,h1,l1; split2(v.x,v.y,h0,l0); split2(v.z,v.w,h1,l1);
            sAh[r*36+cq*2]=h0; sAh[r*36+cq*2+1]=h1;
            sAl[r*36+cq*2]=l0; sAl[r*36+cq*2+1]=l1;
        }
        #pragma unroll
        for(int i=0;i<8;i++){
            int idx=i*256+tid; int r=idx>>5, c=idx&31;
            *(float4*)(sF+r*132+c*4)=*(const float4*)(Eb+(long)(kb+r)*DD+c*4);
        }
        __syncthreads();
        #pragma unroll
        for(int ii=0;ii<16;ii++){
            int n =(ii&3)*32+(wid&3)*8+g;
            int kp=(ii>>2)*8+(wid>>2)*4+q;
            uint32_t h,l; split2(sF[(2*kp)*132+n], sF[(2*kp+1)*132+n], h, l);
            sEh[n*36+kp]=h; sEl[n*36+kp]=l;
        }
        if(tid<64){
            #pragma unroll
            for(int kp=0;kp<32;kp++){
                uint32_t h=sAh[tid*36+kp], l=sAl[tid*36+kp];
                rsum += unpk(h,l,0)+unpk(h,l,1);
            }
        }
        __syncthreads();
        gemm3<2,36,36,4>(sAh,sAl,sEh,sEl,wm,wn,lane,acc);
        __syncthreads();
    }
    FOREACH(2,
        *(float2*)&g_s0[((long)bb*NN+rl)*DD+col] =
            make_float2(acc[f][2*h], acc[f][2*h+1]);
    )
    if(tid<64) g_rs[bb*NN+tid]=rsum;
}
__global__ void __launch_bounds__(128) k_residual(const float* __restrict__ p0){
    int bb=blockIdx.x, d=threadIdx.x;
    float s=0.f;
    #pragma unroll
    for(int c=0;c<16;c++) s += g_respart[(bb*16+c)*DD+d];
    for(int n=0;n<NN;n++) s += p0[((long)bb*NN+n)*DD+d];
    g_resid[bb*DD+d]=s;
}

// ---- persistent fused GRU: 64 rows/block, half-K slabs ----
__global__ void __launch_bounds__(256) k_gru(
    const float* __restrict__ p0in,
    const float* __restrict__ bl, const float* __restrict__ br,
    const float* __restrict__ bz, const float* __restrict__ bh,
    const float* __restrict__ bo, const float* __restrict__ ba1,
    const float* __restrict__ Wa2, const float* __restrict__ ba2,
    float* __restrict__ outO)
{
    extern __shared__ uint32_t sm[];
    uint32_t* T1h=sm;        uint32_t* T1l=sm+4352;
    uint32_t* Tph=sm+8704;   uint32_t* Tpl=sm+13056;
    uint32_t* WBh=sm+17408;  uint32_t* WBl=sm+22016;
    const int tid=threadIdx.x, lane=tid&31, wid=tid>>5;
    const int wm=(wid>>2)*32, wn=(wid&3)*32;
    const long rb=(long)blockIdx.x*64;

    split_tile<64>(T1h,T1l,g_s0+rb*DD,tid);
    float pr[8][4], zf[8][4], acc[8][4], rs4[4];
    FOREACH(2,
        float2 pv=*(const float2*)&p0in[(rb+rl)*DD+col];
        pr[f][2*h]=pv.x; pr[f][2*h+1]=pv.y;
        if(ni==0) rs4[mi*2+h]=g_rs[rb+rl];
    )
    FOREACH(2,
        uint32_t hh; uint32_t ll; split2(pr[f][2*h],pr[f][2*h+1],hh,ll);
        Tph[rl*LDP+(col>>1)]=hh; Tpl[rl*LDP+(col>>1)]=ll;
    )
    __syncthreads();

#define ROUND(sid, hf, Xh, Xl, A) { \
    __syncthreads(); \
    copy_half(WBh,WBl,g_Wpk[sid][0],g_Wpk[sid][1],hf,tid); \
    __syncthreads(); \
    gemm3<2,LDP,36,4>(Xh+32*hf, Xl+32*hf, WBh, WBl, wm, wn, lane, A); }
#define GEMM1(sid, Xh, Xl, A) ROUND(sid,0,Xh,Xl,A) ROUND(sid,1,Xh,Xl,A)

    for(int t=0;t<5;t++){
        ZERO(acc,8); GEMM1(0, T1h, T1l, acc);
        __syncthreads();
        FOREACH(2,
            float2 bv=*(const float2*)&bl[col];
            float v0=acc[f][2*h]+rs4[mi*2+h]*bv.x;
            float v1=acc[f][2*h+1]+rs4[mi*2+h]*bv.y;
            uint32_t hh; uint32_t ll; split2(v0,v1,hh,ll);
            T1h[rl*LDP+(col>>1)]=hh; T1l[rl*LDP+(col>>1)]=ll;
        )
        ZERO(zf,8); GEMM1(1, T1h, T1l, zf); GEMM1(2, Tph, Tpl, zf);
        FOREACH(2,
            float2 bv=*(const float2*)&bz[col];
            zf[f][2*h]=sigf(zf[f][2*h]+bv.x); zf[f][2*h+1]=sigf(zf[f][2*h+1]+bv.y);
        )
        ZERO(acc,8); GEMM1(3, T1h, T1l, acc); GEMM1(4, Tph, Tpl, acc);
        __syncthreads();
        FOREACH(2,
            float2 bv=*(const float2*)&br[col];
            float r0=sigf(acc[f][2*h]+bv.x);
            float r1=sigf(acc[f][2*h+1]+bv.y);
            uint32_t hh; uint32_t ll; split2(r0*pr[f][2*h], r1*pr[f][2*h+1], hh, ll);
            Tph[rl*LDP+(col>>1)]=hh; Tpl[rl*LDP+(col>>1)]=ll;
        )
        ZERO(acc,8); GEMM1(5, T1h, T1l, acc); GEMM1(6, Tph, Tpl, acc);
        FOREACH(2,
            float2 bv=*(const float2*)&bh[col];
            float h0=tanhf(acc[f][2*h]+bv.x);
            float h1=tanhf(acc[f][2*h+1]+bv.y);
            pr[f][2*h]  =(1.f-zf[f][2*h])*pr[f][2*h]+zf[f][2*h]*h0;
            pr[f][2*h+1]=(1.f-zf[f][2*h+1])*pr[f][2*h+1]+zf[f][2*h+1]*h1;
        )
        __syncthreads();
        FOREACH(2,
            uint32_t hh; uint32_t ll; split2(pr[f][2*h],pr[f][2*h+1],hh,ll);
            Tph[rl*LDP+(col>>1)]=hh; Tpl[rl*LDP+(col>>1)]=ll;
        )
    }
    ZERO(acc,8); GEMM1(7, Tph, Tpl, acc);
    FOREACH(2,
        float2 bv=*(const float2*)&bo[col];
        *(float2*)&outO[(rb+rl)*DD+col] =
            make_float2(tanhf(acc[f][2*h]+bv.x), tanhf(acc[f][2*h+1]+bv.y));
    )
    ZERO(acc,8); GEMM1(8, Tph, Tpl, acc);
    __syncthreads();
    float* sT=(float*)sm;
    FOREACH(2,
        float2 bv=*(const float2*)&ba1[col];
        sT[rl*132+col]  =tanhf(acc[f][2*h]+bv.x);
        sT[rl*132+col+1]=tanhf(acc[f][2*h+1]+bv.y);
    )
    __syncthreads();
    if(tid<64){
        float d=0.f;
        #pragma unroll 16
        for(int c=0;c<DD;c++) d += sT[tid*132+c]*Wa2[c];
        g_attl[rb+tid]=d+ba2[0];
    }
}

// ---- final ----
__global__ void __launch_bounds__(128) k_final(const float* __restrict__ outO,
                                               float* __restrict__ res){
    __shared__ float sl[64], se[64];
    const int bb=blockIdx.x, tid=threadIdx.x;
    if(tid<64) sl[tid]=g_attl[bb*NN+tid];
    __syncthreads();
    float mx=-1e30f;
    #pragma unroll
    for(int n=0;n<64;n++) mx=fmaxf(mx,sl[n]);
    if(tid<64) se[tid]=__expf(sl[tid]-mx);
    __syncthreads();
    float sum=0.f;
    #pragma unroll
    for(int n=0;n<64;n++) sum+=se[n];
    const float* ob=outO+(long)bb*NN*DD+tid;
    float ws=0.f;
    #pragma unroll 8
    for(int n=0;n<64;n++) ws+=se[n]*ob[n*DD];
    float g=tanhf(ws/sum);
    float rr=g+g_resid[bb*DD+tid]*(1.f/1088.f);
    res[bb*DD+tid]=fmaxf(rr,0.f);
}

// ---- launch ----
extern "C" void kernel_launch(void* const* d_in, const int* in_sizes, int n_in,
                              void* d_out, int out_size)
{
    const float* in_prop=(const float*)d_in[0];
    const float* in_edge=(const float*)d_in[1];
    const float* in_A  =(const float*)d_in[2];
    const float* Wl =(const float*)d_in[3];
    const float* bl =(const float*)d_in[4];
    const float* Wr =(const float*)d_in[5];
    const float* br =(const float*)d_in[6];
    const float* Wz =(const float*)d_in[7];
    const float* bz =(const float*)d_in[8];
    const float* Wh =(const float*)d_in[9];
    const float* bh =(const float*)d_in[10];
    const float* Wa1=(const float*)d_in[11];
    const float* ba1=(const float*)d_in[12];
    const float* Wa2=(const float*)d_in[13];
    const float* ba2=(const float*)d_in[14];
    const float* Wo =(const float*)d_in[15];
    const float* bo =(const float*)d_in[16];

    float* out =(float*)d_out;
    float* res =out;
    float* outO=out+B*DD;
    float* outE=out+B*DD+(long)BN*DD;

    const int SA_SM=(DD*DD+1024)*4, SB_SM=(2*DD*DD+1024)*4;
    const int S0_SM=22272*4, E5_SM=26112*4, GR_SM=26624*4;
    cudaFuncSetAttribute(k_sqmmA, cudaFuncAttributeMaxDynamicSharedMemorySize, SA_SM);
    cudaFuncSetAttribute(k_sqmmB, cudaFuncAttributeMaxDynamicSharedMemorySize, SB_SM);
    cudaFuncSetAttribute(k_s0,    cudaFuncAttributeMaxDynamicSharedMemorySize, S0_SM);
    cudaFuncSetAttribute(k_e5,    cudaFuncAttributeMaxDynamicSharedMemorySize, E5_SM);
    cudaFuncSetAttribute(k_gru,   cudaFuncAttributeMaxDynamicSharedMemorySize, GR_SM);

    k_prep<<<10,256>>>(Wl,Wr,Wz,Wh,Wo,Wa1,bl);
    k_sqmmA<<<16,1024,SA_SM>>>(Wl);
    k_sqmmB<<<16,1024,SB_SM>>>(Wl);
    k_e5<<<BE/64,256,E5_SM>>>(in_edge,outE);
    k_s0<<<B,256,S0_SM>>>(in_A,in_edge);
    k_gru<<<BN/64,256,GR_SM>>>(in_prop,bl,br,bz,bh,bo,ba1,Wa2,ba2,outO);
    k_residual<<<B,128>>>(in_prop);
    k_final<<<B,128>>>(outO,res);
}